// round 2
// baseline (speedup 1.0000x reference)
#include <cuda_runtime.h>

#define HH   64
#define WW   64
#define CIN  512
#define COUT 512
#define NB   16
#define EPSF 1e-8f

// Scratch (allocation-free rule: __device__ globals)
__device__ float g_wt[9 * CIN * COUT];   // [kh*3+kw][c][o]
__device__ float g_w2[CIN * COUT];       // [c][o] : sum_{kh,kw} w^2
__device__ float g_d [NB * COUT];        // [n][o] : demod coeff

// ---------------------------------------------------------------------------
// Kernel 1: weight transpose + per-(o,c) squared sum
// ---------------------------------------------------------------------------
__global__ void prep_kernel(const float* __restrict__ w) {
    int idx = blockIdx.x * 256 + threadIdx.x;
    if (idx >= CIN * COUT) return;
    int o = idx % COUT;          // fastest -> coalesced writes in o
    int c = idx / COUT;
    const float* wp = w + ((size_t)o * CIN + c) * 9;
    float sum = 0.f;
#pragma unroll
    for (int t = 0; t < 9; ++t) {
        float v = wp[t];
        sum += v * v;
        g_wt[(size_t)t * CIN * COUT + (size_t)c * COUT + o] = v;
    }
    g_w2[(size_t)c * COUT + o] = sum;
}

// ---------------------------------------------------------------------------
// Kernel 2: d[n][o] = rsqrt( sum_c s[n,c]^2 * w2[c,o] + eps )
// grid (COUT/128, NB), 128 threads
// ---------------------------------------------------------------------------
__global__ void d_kernel(const float* __restrict__ s) {
    int n = blockIdx.y;
    int o = blockIdx.x * 128 + threadIdx.x;
    __shared__ float s2[CIN];
    for (int i = threadIdx.x; i < CIN; i += 128) {
        float v = s[n * CIN + i];
        s2[i] = v * v;
    }
    __syncthreads();
    float acc = 0.f;
#pragma unroll 8
    for (int c = 0; c < CIN; ++c)
        acc += s2[c] * g_w2[(size_t)c * COUT + o];
    g_d[n * COUT + o] = rsqrtf(acc + EPSF);
}

// ---------------------------------------------------------------------------
// Kernel 3: main modulated conv (implicit GEMM)
// block = (o-tile of 64, one image row h, sample n); 256 threads, 4x4 microtile
// ---------------------------------------------------------------------------
__global__ __launch_bounds__(256)
void conv_kernel(const float* __restrict__ x,
                 const float* __restrict__ s,
                 const float* __restrict__ noise,
                 const float* __restrict__ bias,
                 float* __restrict__ out) {
    const int o0  = blockIdx.x * 64;
    const int h   = blockIdx.y;
    const int n   = blockIdx.z;
    const int tid = threadIdx.x;
    const int tp  = tid & 15;   // pixel fragment index  (4 px each)
    const int to  = tid >> 4;   // out-channel fragment  (4 oc each)

    __shared__ float s_sh[CIN];
    __shared__ float Ws[16][64];   // [k][o]
    __shared__ float Xs[16][64];   // [k][p]

    float acc[4][4];
#pragma unroll
    for (int i = 0; i < 4; ++i)
#pragma unroll
        for (int j = 0; j < 4; ++j) acc[i][j] = 0.f;

    // cache per-sample modulation
    for (int i = tid; i < CIN; i += 256) s_sh[i] = s[n * CIN + i];
    __syncthreads();

    const float* xn = x + (size_t)n * CIN * HH * WW;

    const int p    = tid & 63;   // pixel lane for X loads
    const int cc0  = tid >> 6;   // 0..3

    for (int kh = 0; kh < 3; ++kh) {
        const int  hh  = h + kh - 1;
        const bool hok = (hh >= 0) && (hh < HH);
        for (int kw = 0; kw < 3; ++kw) {
            const float* wt = g_wt + (size_t)(kh * 3 + kw) * CIN * COUT;
            const int  ww  = p + kw - 1;
            const bool pok = hok && (ww >= 0) && (ww < WW);

            for (int c0 = 0; c0 < CIN; c0 += 16) {
                __syncthreads();   // protect previous tile's reads
                // ---- load W tile: 16c x 64o, coalesced in o ----
#pragma unroll
                for (int r = 0; r < 4; ++r) {
                    int e  = tid + r * 256;
                    int cc = e >> 6;
                    int o  = e & 63;
                    Ws[cc][o] = wt[(size_t)(c0 + cc) * COUT + o0 + o];
                }
                // ---- load modulated X tile: 16c x 64px (with zero pad) ----
#pragma unroll
                for (int r = 0; r < 4; ++r) {
                    int cc = cc0 * 4 + r;
                    float v = 0.f;
                    if (pok)
                        v = xn[(size_t)(c0 + cc) * HH * WW + hh * WW + ww]
                            * s_sh[c0 + cc];
                    Xs[cc][p] = v;
                }
                __syncthreads();
                // ---- 16-step rank-1 updates, 4x4 microtile ----
#pragma unroll
                for (int k = 0; k < 16; ++k) {
                    float4 wf = *(const float4*)&Ws[k][to * 4];
                    float4 xf = *(const float4*)&Xs[k][tp * 4];
                    acc[0][0] += wf.x * xf.x; acc[0][1] += wf.x * xf.y;
                    acc[0][2] += wf.x * xf.z; acc[0][3] += wf.x * xf.w;
                    acc[1][0] += wf.y * xf.x; acc[1][1] += wf.y * xf.y;
                    acc[1][2] += wf.y * xf.z; acc[1][3] += wf.y * xf.w;
                    acc[2][0] += wf.z * xf.x; acc[2][1] += wf.z * xf.y;
                    acc[2][2] += wf.z * xf.z; acc[2][3] += wf.z * xf.w;
                    acc[3][0] += wf.w * xf.x; acc[3][1] += wf.w * xf.y;
                    acc[3][2] += wf.w * xf.z; acc[3][3] += wf.w * xf.w;
                }
            }
        }
    }

    // ---- epilogue: demod, bias, noise, LeakyReLU(0.2); vectorized stores ----
#pragma unroll
    for (int i = 0; i < 4; ++i) {
        const int o = o0 + to * 4 + i;
        const float dd = g_d[n * COUT + o];
        const float bb = bias[o];
        const size_t base = (((size_t)n * COUT + o) * HH + h) * WW + tp * 4;
        float4 nz = *(const float4*)&noise[base];
        float4 r;
        r.x = acc[i][0] * dd + bb + nz.x;
        r.y = acc[i][1] * dd + bb + nz.y;
        r.z = acc[i][2] * dd + bb + nz.z;
        r.w = acc[i][3] * dd + bb + nz.w;
        r.x = (r.x >= 0.f) ? r.x : 0.2f * r.x;
        r.y = (r.y >= 0.f) ? r.y : 0.2f * r.y;
        r.z = (r.z >= 0.f) ? r.z : 0.2f * r.z;
        r.w = (r.w >= 0.f) ? r.w : 0.2f * r.w;
        *(float4*)&out[base] = r;
    }
}

// ---------------------------------------------------------------------------
extern "C" void kernel_launch(void* const* d_in, const int* in_sizes, int n_in,
                              void* d_out, int out_size) {
    const float* x     = (const float*)d_in[0];  // [16,512,64,64]
    const float* s     = (const float*)d_in[1];  // [16,512]
    const float* noise = (const float*)d_in[2];  // [16,512,64,64]
    const float* w     = (const float*)d_in[3];  // [512,512,3,3]
    const float* b     = (const float*)d_in[4];  // [512]
    float* out = (float*)d_out;

    // 1) weight transpose + w^2 reduction
    prep_kernel<<<(CIN * COUT + 255) / 256, 256>>>(w);
    // 2) demodulation coefficients
    d_kernel<<<dim3(COUT / 128, NB), 128>>>(s);
    // 3) main conv
    conv_kernel<<<dim3(COUT / 64, HH, NB), 256>>>(x, s, noise, b, out);
}

// round 5
// speedup vs baseline: 5.3818x; 5.3818x over previous
#include <cuda_runtime.h>
#include <cuda_fp16.h>
#include <cstdint>

#define HH    64
#define WW    64
#define CIN   512
#define COUT  512
#define NB    16
#define EPSF  1e-8f

// ---------------- scratch (__device__ globals) -----------------------------
__device__ __half g_xhi[(size_t)NB * HH * WW * CIN];   // [n][h][w][c]
__device__ __half g_xlo[(size_t)NB * HH * WW * CIN];
__device__ __half g_whi[(size_t)9 * COUT * CIN];       // [t][o][c]
__device__ __half g_wlo[(size_t)9 * COUT * CIN];
__device__ float  g_w2 [(size_t)CIN * COUT];           // [c][o]
__device__ float  g_d  [(size_t)NB * COUT];            // [n][o]

// ---------------- helpers --------------------------------------------------
__device__ __forceinline__ uint32_t smem_to_u32(const void* p) {
    uint32_t a;
    asm("{ .reg .u64 t; cvta.to.shared.u64 t, %1; cvt.u32.u64 %0, t; }"
        : "=r"(a) : "l"(p));
    return a;
}
__device__ __forceinline__ void cpa16(uint32_t dst, const void* src, bool ok) {
    asm volatile("cp.async.cg.shared.global [%0], [%1], 16, %2;"
                 :: "r"(dst), "l"(src), "r"(ok ? 16u : 0u) : "memory");
}
#define CP_COMMIT() asm volatile("cp.async.commit_group;" ::: "memory")
#define CP_WAIT1()  asm volatile("cp.async.wait_group 1;" ::: "memory")

#define LDSM_X4(r, addr) \
    asm volatile("ldmatrix.sync.aligned.m8n8.x4.shared.b16 {%0,%1,%2,%3}, [%4];" \
        : "=r"((r)[0]), "=r"((r)[1]), "=r"((r)[2]), "=r"((r)[3]) : "r"(addr))
#define LDSM_X2(r, addr) \
    asm volatile("ldmatrix.sync.aligned.m8n8.x2.shared.b16 {%0,%1}, [%2];" \
        : "=r"((r)[0]), "=r"((r)[1]) : "r"(addr))
#define MMA16816(c, a, b) \
    asm volatile("mma.sync.aligned.m16n8k16.row.col.f32.f16.f16.f32 " \
        "{%0,%1,%2,%3}, {%4,%5,%6,%7}, {%8,%9}, {%0,%1,%2,%3};" \
        : "+f"((c)[0]), "+f"((c)[1]), "+f"((c)[2]), "+f"((c)[3]) \
        : "r"((a)[0]), "r"((a)[1]), "r"((a)[2]), "r"((a)[3]), \
          "r"((b)[0]), "r"((b)[1]))

// ---------------------------------------------------------------------------
// prep_x: x_mod = x * s  ->  [n][h][w][c] fp16 hi/lo (tiled transpose)
// ---------------------------------------------------------------------------
__global__ __launch_bounds__(256) void prep_x_kernel(const float* __restrict__ x,
                                                     const float* __restrict__ s) {
    const int cb = blockIdx.x, h = blockIdx.y, n = blockIdx.z;
    __shared__ float tile[64][65];
    const int tid = threadIdx.x;
#pragma unroll
    for (int it = 0; it < 16; ++it) {
        int idx = it * 256 + tid;
        int c = idx >> 6, wq = idx & 63;
        float sv = s[n * CIN + cb * 64 + c];
        tile[c][wq] = x[(((size_t)n * CIN + cb * 64 + c) * HH + h) * WW + wq] * sv;
    }
    __syncthreads();
#pragma unroll
    for (int it = 0; it < 8; ++it) {
        int idx = it * 256 + tid;
        int cp = idx & 31, wq = idx >> 5;
        float v0 = tile[2 * cp][wq], v1 = tile[2 * cp + 1][wq];
        __half h0 = __float2half_rn(v0);
        __half h1 = __float2half_rn(v1);
        __half l0 = __float2half_rn(v0 - __half2float(h0));
        __half l1 = __float2half_rn(v1 - __half2float(h1));
        size_t off = (((size_t)n * HH + h) * WW + wq) * CIN + cb * 64 + 2 * cp;
        *(__half2*)(g_xhi + off) = __half2(h0, h1);
        *(__half2*)(g_xlo + off) = __half2(l0, l1);
    }
}

// ---------------------------------------------------------------------------
// prep_w: w -> [t][o][c] fp16 hi/lo + w2[c][o]
// ---------------------------------------------------------------------------
__global__ __launch_bounds__(256) void prep_w_kernel(const float* __restrict__ w) {
    int idx = blockIdx.x * 256 + threadIdx.x;
    if (idx >= CIN * COUT) return;
    int c = idx & 511, o = idx >> 9;
    const float* wp = w + ((size_t)o * CIN + c) * 9;
    float sum = 0.f;
#pragma unroll
    for (int t = 0; t < 9; ++t) {
        float v = wp[t];
        sum += v * v;
        __half hi = __float2half_rn(v);
        __half lo = __float2half_rn(v - __half2float(hi));
        size_t off = ((size_t)t * COUT + o) * CIN + c;
        g_whi[off] = hi;
        g_wlo[off] = lo;
    }
    g_w2[(size_t)c * COUT + o] = sum;
}

// ---------------------------------------------------------------------------
// d_kernel
// ---------------------------------------------------------------------------
__global__ void d_kernel(const float* __restrict__ s) {
    int n = blockIdx.y;
    int o = blockIdx.x * 128 + threadIdx.x;
    __shared__ float s2[CIN];
    for (int i = threadIdx.x; i < CIN; i += 128) {
        float v = s[n * CIN + i];
        s2[i] = v * v;
    }
    __syncthreads();
    float acc = 0.f;
#pragma unroll 8
    for (int c = 0; c < CIN; ++c) acc += s2[c] * g_w2[(size_t)c * COUT + o];
    g_d[n * COUT + o] = rsqrtf(acc + EPSF);
}

// ---------------------------------------------------------------------------
// main HMMA conv kernel
// CTA = (128 outs, 128 pixels = 2 rows, n); 256 threads = 8 warps (2x4)
// ---------------------------------------------------------------------------
#define AST     80                    // bytes per smem row (32 halves + pad)
#define TILE_B  (128 * AST)           // 10240 per matrix
#define STG     (4 * TILE_B)          // Ahi|Alo|Bhi|Blo = 40960
#define NSTG    3
#define SM_DYN  (1024 + NSTG * STG)   // dd(512) bb(512) + buffers

__global__ __launch_bounds__(256, 1)
void conv_mma_kernel(const float* __restrict__ noise,
                     const float* __restrict__ bias,
                     float* __restrict__ out) {
    extern __shared__ char smem[];
    float* dd = (float*)smem;          // 128 floats
    float* bb = dd + 128;              // 128 floats
    char*  bufs = smem + 1024;
    const uint32_t sb = smem_to_u32(bufs);

    const int tid = threadIdx.x;
    const int lid = tid & 31, wid = tid >> 5;
    const int wm = wid >> 2, wn = wid & 3;       // 2 x 4 warp grid
    const int o0 = blockIdx.x * 128;
    const int by = blockIdx.y;                   // rows 2by, 2by+1
    const int n  = blockIdx.z;

    if (tid < 128) {
        dd[tid] = g_d[n * COUT + o0 + tid];
        bb[tid] = bias[o0 + tid];
    }

    const __half* xh = g_xhi + (size_t)n * HH * WW * CIN;
    const __half* xl = g_xlo + (size_t)n * HH * WW * CIN;

    // per-thread load slots: slot = j*256 + tid, row = slot>>2, chunk q = slot&3
    const int p0 = tid >> 2, q0 = tid & 3;       // j=0
    const int p1 = (tid + 256) >> 2;             // j=1 (q same: q0)

    // ldmatrix per-thread offsets
    const uint32_t aoff = (uint32_t)((wm * 64 + (lid & 7) + ((lid >> 3) & 1) * 8) * AST
                                     + (lid >> 4) * 16);
    const uint32_t boff = (uint32_t)((wn * 32 + (lid & 7)) * AST + ((lid >> 3) & 1) * 16);

    float C[4][4][4];
#pragma unroll
    for (int i = 0; i < 4; ++i)
#pragma unroll
        for (int j = 0; j < 4; ++j)
#pragma unroll
            for (int k = 0; k < 4; ++k) C[i][j][k] = 0.f;

    // ---- prefetch macro: stage st into buffer st%3 ----
#define PREFETCH(st) do {                                                        \
    const int t_  = (st) >> 4;                                                   \
    const int cb_ = (st) & 15;                                                   \
    const int kh_ = t_ / 3, kw_ = t_ % 3;                                        \
    uint32_t base_ = sb + ((st) % NSTG) * STG;                                   \
    /* A rows (2 slots) */                                                       \
    {                                                                            \
        int hh0 = 2 * by + (p0 >> 6) + kh_ - 1, ww0 = (p0 & 63) + kw_ - 1;       \
        bool ok0 = (hh0 >= 0) & (hh0 < HH) & (ww0 >= 0) & (ww0 < WW);            \
        int gi0 = ok0 ? ((hh0 * WW + ww0) * CIN + cb_ * 32 + q0 * 8) : 0;        \
        uint32_t d0 = base_ + p0 * AST + q0 * 16;                                \
        cpa16(d0,          xh + gi0, ok0);                                       \
        cpa16(d0 + TILE_B, xl + gi0, ok0);                                       \
        int hh1 = 2 * by + (p1 >> 6) + kh_ - 1, ww1 = (p1 & 63) + kw_ - 1;       \
        bool ok1 = (hh1 >= 0) & (hh1 < HH) & (ww1 >= 0) & (ww1 < WW);            \
        int gi1 = ok1 ? ((hh1 * WW + ww1) * CIN + cb_ * 32 + q0 * 8) : 0;        \
        uint32_t d1 = base_ + p1 * AST + q0 * 16;                                \
        cpa16(d1,          xh + gi1, ok1);                                       \
        cpa16(d1 + TILE_B, xl + gi1, ok1);                                       \
    }                                                                            \
    /* B rows (2 slots) */                                                       \
    {                                                                            \
        size_t wb = ((size_t)t_ * COUT + o0) * CIN + cb_ * 32 + q0 * 8;          \
        uint32_t d0 = base_ + 2 * TILE_B + p0 * AST + q0 * 16;                   \
        cpa16(d0,          g_whi + wb + (size_t)p0 * CIN, true);                 \
        cpa16(d0 + TILE_B, g_wlo + wb + (size_t)p0 * CIN, true);                 \
        uint32_t d1 = base_ + 2 * TILE_B + p1 * AST + q0 * 16;                   \
        cpa16(d1,          g_whi + wb + (size_t)p1 * CIN, true);                 \
        cpa16(d1 + TILE_B, g_wlo + wb + (size_t)p1 * CIN, true);                 \
    }                                                                            \
} while (0)

    PREFETCH(0); CP_COMMIT();
    PREFETCH(1); CP_COMMIT();

#pragma unroll 1
    for (int s = 0; s < 144; ++s) {
        CP_WAIT1();
        __syncthreads();

        const uint32_t ahi = sb + (s % NSTG) * STG;
        const uint32_t alo = ahi + TILE_B;
        const uint32_t bhi = ahi + 2 * TILE_B;
        const uint32_t blo = ahi + 3 * TILE_B;

#pragma unroll
        for (int kc = 0; kc < 2; ++kc) {
            uint32_t ahf[4][4], alf[4][4], bhf[4][2], blf[4][2];
#pragma unroll
            for (int mt = 0; mt < 4; ++mt) {
                uint32_t a = aoff + mt * (16 * AST) + kc * 32;
                LDSM_X4(ahf[mt], ahi + a);
                LDSM_X4(alf[mt], alo + a);
            }
#pragma unroll
            for (int nt = 0; nt < 4; ++nt) {
                uint32_t b = boff + nt * (8 * AST) + kc * 32;
                LDSM_X2(bhf[nt], bhi + b);
                LDSM_X2(blf[nt], blo + b);
            }
#pragma unroll
            for (int mt = 0; mt < 4; ++mt)
#pragma unroll
                for (int nt = 0; nt < 4; ++nt) {
                    MMA16816(C[mt][nt], ahf[mt], bhf[nt]);
                    MMA16816(C[mt][nt], ahf[mt], blf[nt]);
                    MMA16816(C[mt][nt], alf[mt], bhf[nt]);
                }
        }

        if (s + 2 < 144) PREFETCH(s + 2);
        CP_COMMIT();
    }
#undef PREFETCH

    // ---- epilogue: demod, bias, noise, LeakyReLU ----
#pragma unroll
    for (int mt = 0; mt < 4; ++mt)
#pragma unroll
        for (int nt = 0; nt < 4; ++nt)
#pragma unroll
            for (int i = 0; i < 4; ++i) {
                int m = wm * 64 + mt * 16 + (lid >> 2) + (i >> 1) * 8;
                int o = wn * 32 + nt * 8 + (lid & 3) * 2 + (i & 1);
                int h = 2 * by + (m >> 6);
                int wq = m & 63;
                size_t oa = (((size_t)n * COUT + o0 + o) * HH + h) * WW + wq;
                float v = C[mt][nt][i] * dd[o] + bb[o] + noise[oa];
                out[oa] = (v >= 0.f) ? v : 0.2f * v;
            }
}

// ---------------------------------------------------------------------------
extern "C" void kernel_launch(void* const* d_in, const int* in_sizes, int n_in,
                              void* d_out, int out_size) {
    const float* x     = (const float*)d_in[0];
    const float* s     = (const float*)d_in[1];
    const float* noise = (const float*)d_in[2];
    const float* w     = (const float*)d_in[3];
    const float* b     = (const float*)d_in[4];
    float* out = (float*)d_out;

    cudaFuncSetAttribute(conv_mma_kernel,
                         cudaFuncAttributeMaxDynamicSharedMemorySize, SM_DYN);

    prep_x_kernel<<<dim3(8, 64, 16), 256>>>(x, s);
    prep_w_kernel<<<(CIN * COUT + 255) / 256, 256>>>(w);
    d_kernel<<<dim3(COUT / 128, NB), 128>>>(s);
    conv_mma_kernel<<<dim3(COUT / 128, HH / 2, NB), 256, SM_DYN>>>(noise, b, out);
}

// round 6
// speedup vs baseline: 6.1626x; 1.1451x over previous
#include <cuda_runtime.h>
#include <cuda_fp16.h>
#include <cstdint>

#define HH    64
#define WW    64
#define CIN   512
#define COUT  512
#define NB    16
#define EPSF  1e-8f

// ---------------- scratch (__device__ globals) -----------------------------
__device__ __half g_xhi[(size_t)NB * HH * WW * CIN];   // [n][h][w][c]
__device__ __half g_xlo[(size_t)NB * HH * WW * CIN];
__device__ __half g_whi[(size_t)9 * COUT * CIN];       // [t][o][c]
__device__ __half g_wlo[(size_t)9 * COUT * CIN];
__device__ float  g_w2 [(size_t)CIN * COUT];           // [c][o]
__device__ float  g_d  [(size_t)NB * COUT];            // [n][o]

// ---------------- helpers --------------------------------------------------
__device__ __forceinline__ uint32_t smem_to_u32(const void* p) {
    uint32_t a;
    asm("{ .reg .u64 t; cvta.to.shared.u64 t, %1; cvt.u32.u64 %0, t; }"
        : "=r"(a) : "l"(p));
    return a;
}
__device__ __forceinline__ void cpa16(uint32_t dst, const void* src, bool ok) {
    asm volatile("cp.async.cg.shared.global [%0], [%1], 16, %2;"
                 :: "r"(dst), "l"(src), "r"(ok ? 16u : 0u) : "memory");
}
#define CP_COMMIT() asm volatile("cp.async.commit_group;" ::: "memory")
#define CP_WAIT1()  asm volatile("cp.async.wait_group 1;" ::: "memory")

#define LDSM_X4(r, addr) \
    asm volatile("ldmatrix.sync.aligned.m8n8.x4.shared.b16 {%0,%1,%2,%3}, [%4];" \
        : "=r"((r)[0]), "=r"((r)[1]), "=r"((r)[2]), "=r"((r)[3]) : "r"(addr))
#define LDSM_X2(r, addr) \
    asm volatile("ldmatrix.sync.aligned.m8n8.x2.shared.b16 {%0,%1}, [%2];" \
        : "=r"((r)[0]), "=r"((r)[1]) : "r"(addr))
#define MMA16816(c, a, b) \
    asm volatile("mma.sync.aligned.m16n8k16.row.col.f32.f16.f16.f32 " \
        "{%0,%1,%2,%3}, {%4,%5,%6,%7}, {%8,%9}, {%0,%1,%2,%3};" \
        : "+f"((c)[0]), "+f"((c)[1]), "+f"((c)[2]), "+f"((c)[3]) \
        : "r"((a)[0]), "r"((a)[1]), "r"((a)[2]), "r"((a)[3]), \
          "r"((b)[0]), "r"((b)[1]))

// ---------------------------------------------------------------------------
// prep_x: x_mod = x * s  ->  [n][h][w][c] fp16 hi/lo (tiled transpose)
// ---------------------------------------------------------------------------
__global__ __launch_bounds__(256) void prep_x_kernel(const float* __restrict__ x,
                                                     const float* __restrict__ s) {
    const int cb = blockIdx.x, h = blockIdx.y, n = blockIdx.z;
    __shared__ float tile[64][65];
    const int tid = threadIdx.x;
#pragma unroll
    for (int it = 0; it < 16; ++it) {
        int idx = it * 256 + tid;
        int c = idx >> 6, wq = idx & 63;
        float sv = s[n * CIN + cb * 64 + c];
        tile[c][wq] = x[(((size_t)n * CIN + cb * 64 + c) * HH + h) * WW + wq] * sv;
    }
    __syncthreads();
#pragma unroll
    for (int it = 0; it < 8; ++it) {
        int idx = it * 256 + tid;
        int cp = idx & 31, wq = idx >> 5;
        float v0 = tile[2 * cp][wq], v1 = tile[2 * cp + 1][wq];
        __half h0 = __float2half_rn(v0);
        __half h1 = __float2half_rn(v1);
        __half l0 = __float2half_rn(v0 - __half2float(h0));
        __half l1 = __float2half_rn(v1 - __half2float(h1));
        size_t off = (((size_t)n * HH + h) * WW + wq) * CIN + cb * 64 + 2 * cp;
        *(__half2*)(g_xhi + off) = __half2(h0, h1);
        *(__half2*)(g_xlo + off) = __half2(l0, l1);
    }
}

// ---------------------------------------------------------------------------
// prep_w: w -> [t][o][c] fp16 hi/lo + w2[c][o]
// ---------------------------------------------------------------------------
__global__ __launch_bounds__(256) void prep_w_kernel(const float* __restrict__ w) {
    int idx = blockIdx.x * 256 + threadIdx.x;
    if (idx >= CIN * COUT) return;
    int c = idx & 511, o = idx >> 9;
    const float* wp = w + ((size_t)o * CIN + c) * 9;
    float sum = 0.f;
#pragma unroll
    for (int t = 0; t < 9; ++t) {
        float v = wp[t];
        sum += v * v;
        __half hi = __float2half_rn(v);
        __half lo = __float2half_rn(v - __half2float(hi));
        size_t off = ((size_t)t * COUT + o) * CIN + c;
        g_whi[off] = hi;
        g_wlo[off] = lo;
    }
    g_w2[(size_t)c * COUT + o] = sum;
}

// ---------------------------------------------------------------------------
// d_kernel
// ---------------------------------------------------------------------------
__global__ void d_kernel(const float* __restrict__ s) {
    int n = blockIdx.y;
    int o = blockIdx.x * 128 + threadIdx.x;
    __shared__ float s2[CIN];
    for (int i = threadIdx.x; i < CIN; i += 128) {
        float v = s[n * CIN + i];
        s2[i] = v * v;
    }
    __syncthreads();
    float acc = 0.f;
#pragma unroll 8
    for (int c = 0; c < CIN; ++c) acc += s2[c] * g_w2[(size_t)c * COUT + o];
    g_d[n * COUT + o] = rsqrtf(acc + EPSF);
}

// ---------------------------------------------------------------------------
// main HMMA conv kernel
// CTA = (128 outs, 256 pixels = 4 rows, n); 8 warps 4x2, warp = 64px x 64o
// ---------------------------------------------------------------------------
#define AST     80                     // bytes per smem row (32 halves + pad)
#define A_B     (256 * AST)            // 20480 per A matrix
#define B_B     (128 * AST)            // 10240 per B matrix
#define STG     (2 * A_B + 2 * B_B)    // Ahi|Alo|Bhi|Blo = 61440
#define NSTG    3
#define SM_DYN  (1024 + NSTG * STG)

__global__ __launch_bounds__(256, 1)
void conv_mma_kernel(const float* __restrict__ noise,
                     const float* __restrict__ bias,
                     float* __restrict__ out) {
    extern __shared__ char smem[];
    float* dd = (float*)smem;          // 128 floats
    float* bb = dd + 128;              // 128 floats
    char*  bufs = smem + 1024;
    const uint32_t sb = smem_to_u32(bufs);

    const int tid = threadIdx.x;
    const int lid = tid & 31, wid = tid >> 5;
    const int wm = wid >> 1, wn = wid & 1;       // 4 x 2 warp grid
    const int o0 = blockIdx.x * 128;
    const int by = blockIdx.y;                   // image rows 4by .. 4by+3
    const int n  = blockIdx.z;

    if (tid < 128) {
        dd[tid] = g_d[n * COUT + o0 + tid];
        bb[tid] = bias[o0 + tid];
    }

    const __half* xh = g_xhi + (size_t)n * HH * WW * CIN;
    const __half* xl = g_xlo + (size_t)n * HH * WW * CIN;

    const int q0 = tid & 3;                      // 16B chunk
    const int pr = tid >> 2;                     // base row (0..63)

    // ldmatrix per-thread base offsets
    const uint32_t aoff = (uint32_t)((wm * 64 + (lid & 15)) * AST + (lid >> 4) * 16);
    const uint32_t boff = (uint32_t)((wn * 64 + (lid & 7)) * AST + ((lid >> 3) & 1) * 16);

    float C[4][8][4];
#pragma unroll
    for (int i = 0; i < 4; ++i)
#pragma unroll
        for (int j = 0; j < 8; ++j)
#pragma unroll
            for (int k = 0; k < 4; ++k) C[i][j][k] = 0.f;

    // ---- prefetch: stage st -> buffer st%3 ----
    // A: 1024 slots (256 rows x 4 chunks), threads do 4 rows (stride 64)
    // B: 512 slots  (128 rows x 4 chunks), threads do 2 rows (stride 64)
#define PREFETCH(st) do {                                                        \
    const int t_  = (st) >> 4;                                                   \
    const int cb_ = (st) & 15;                                                   \
    const int kh_ = t_ / 3, kw_ = t_ % 3;                                        \
    uint32_t base_ = sb + ((st) % NSTG) * STG;                                   \
    _Pragma("unroll")                                                            \
    for (int j = 0; j < 4; ++j) {                                                \
        int p  = j * 64 + pr;                                                    \
        int hh = 4 * by + (p >> 6) + kh_ - 1, ww = (p & 63) + kw_ - 1;           \
        bool ok = (hh >= 0) & (hh < HH) & (ww >= 0) & (ww < WW);                 \
        int gi = ok ? ((hh * WW + ww) * CIN + cb_ * 32 + q0 * 8) : 0;            \
        uint32_t d0 = base_ + p * AST + q0 * 16;                                 \
        cpa16(d0,       xh + gi, ok);                                            \
        cpa16(d0 + A_B, xl + gi, ok);                                            \
    }                                                                            \
    _Pragma("unroll")                                                            \
    for (int j = 0; j < 2; ++j) {                                                \
        int r = j * 64 + pr;                                                     \
        size_t wb = ((size_t)t_ * COUT + o0 + r) * CIN + cb_ * 32 + q0 * 8;      \
        uint32_t d0 = base_ + 2 * A_B + r * AST + q0 * 16;                       \
        cpa16(d0,       g_whi + wb, true);                                       \
        cpa16(d0 + B_B, g_wlo + wb, true);                                       \
    }                                                                            \
} while (0)

    PREFETCH(0); CP_COMMIT();
    PREFETCH(1); CP_COMMIT();

#pragma unroll 1
    for (int s = 0; s < 144; ++s) {
        CP_WAIT1();
        __syncthreads();

        const uint32_t ahi = sb + (s % NSTG) * STG;
        const uint32_t alo = ahi + A_B;
        const uint32_t bhi = ahi + 2 * A_B;
        const uint32_t blo = bhi + B_B;

#pragma unroll
        for (int kc = 0; kc < 2; ++kc) {
            uint32_t bhf[8][2], blf[8][2];
#pragma unroll
            for (int nt = 0; nt < 8; ++nt) {
                uint32_t b = boff + nt * (8 * AST) + kc * 32;
                LDSM_X2(bhf[nt], bhi + b);
                LDSM_X2(blf[nt], blo + b);
            }
            uint32_t ahf[4][4], alf[4][4];
#pragma unroll
            for (int mt = 0; mt < 4; ++mt) {
                uint32_t a = aoff + mt * (16 * AST) + kc * 32;
                LDSM_X4(ahf[mt], ahi + a);
                LDSM_X4(alf[mt], alo + a);
            }
#pragma unroll
            for (int mt = 0; mt < 4; ++mt)
#pragma unroll
                for (int nt = 0; nt < 8; ++nt) {
                    MMA16816(C[mt][nt], ahf[mt], bhf[nt]);
                    MMA16816(C[mt][nt], ahf[mt], blf[nt]);
                    MMA16816(C[mt][nt], alf[mt], bhf[nt]);
                }
        }

        if (s + 2 < 144) PREFETCH(s + 2);
        CP_COMMIT();
    }
#undef PREFETCH

    // ---- epilogue: demod, bias, noise, LeakyReLU ----
#pragma unroll
    for (int mt = 0; mt < 4; ++mt)
#pragma unroll
        for (int nt = 0; nt < 8; ++nt)
#pragma unroll
            for (int i = 0; i < 4; ++i) {
                int m = wm * 64 + mt * 16 + (lid >> 2) + (i >> 1) * 8;
                int o = wn * 64 + nt * 8 + (lid & 3) * 2 + (i & 1);
                int h = 4 * by + (m >> 6);
                int wq = m & 63;
                size_t oa = (((size_t)n * COUT + o0 + o) * HH + h) * WW + wq;
                float v = C[mt][nt][i] * dd[o] + bb[o] + noise[oa];
                out[oa] = (v >= 0.f) ? v : 0.2f * v;
            }
}

// ---------------------------------------------------------------------------
extern "C" void kernel_launch(void* const* d_in, const int* in_sizes, int n_in,
                              void* d_out, int out_size) {
    const float* x     = (const float*)d_in[0];
    const float* s     = (const float*)d_in[1];
    const float* noise = (const float*)d_in[2];
    const float* w     = (const float*)d_in[3];
    const float* b     = (const float*)d_in[4];
    float* out = (float*)d_out;

    cudaFuncSetAttribute(conv_mma_kernel,
                         cudaFuncAttributeMaxDynamicSharedMemorySize, SM_DYN);

    prep_x_kernel<<<dim3(8, 64, 16), 256>>>(x, s);
    prep_w_kernel<<<(CIN * COUT + 255) / 256, 256>>>(w);
    d_kernel<<<dim3(COUT / 128, NB), 128>>>(s);
    conv_mma_kernel<<<dim3(COUT / 128, HH / 4, NB), 256, SM_DYN>>>(noise, b, out);
}

// round 7
// speedup vs baseline: 7.1287x; 1.1568x over previous
#include <cuda_runtime.h>
#include <cuda_fp16.h>
#include <cstdint>

#define HH    64
#define WW    64
#define CIN   512
#define COUT  512
#define NB    16
#define EPSF  1e-8f

// ---------------- scratch (__device__ globals) -----------------------------
__device__ __half g_xhi[(size_t)NB * HH * WW * CIN];   // [n][h][w][c]
__device__ __half g_xlo[(size_t)NB * HH * WW * CIN];
__device__ __half g_whi[(size_t)9 * COUT * CIN];       // [t][o][c]
__device__ __half g_wlo[(size_t)9 * COUT * CIN];
__device__ float  g_w2 [(size_t)CIN * COUT];           // [c][o]
__device__ float  g_d  [(size_t)NB * COUT];            // [n][o]

// ---------------- helpers --------------------------------------------------
__device__ __forceinline__ uint32_t smem_to_u32(const void* p) {
    uint32_t a;
    asm("{ .reg .u64 t; cvta.to.shared.u64 t, %1; cvt.u32.u64 %0, t; }"
        : "=r"(a) : "l"(p));
    return a;
}
__device__ __forceinline__ void cpa16(uint32_t dst, const void* src, bool ok) {
    asm volatile("cp.async.cg.shared.global [%0], [%1], 16, %2;"
                 :: "r"(dst), "l"(src), "r"(ok ? 16u : 0u) : "memory");
}
#define CP_COMMIT() asm volatile("cp.async.commit_group;" ::: "memory")
#define CP_WAIT1()  asm volatile("cp.async.wait_group 1;" ::: "memory")

#define LDSM_X4(r, addr) \
    asm volatile("ldmatrix.sync.aligned.m8n8.x4.shared.b16 {%0,%1,%2,%3}, [%4];" \
        : "=r"((r)[0]), "=r"((r)[1]), "=r"((r)[2]), "=r"((r)[3]) : "r"(addr))
#define LDSM_X2(r, addr) \
    asm volatile("ldmatrix.sync.aligned.m8n8.x2.shared.b16 {%0,%1}, [%2];" \
        : "=r"((r)[0]), "=r"((r)[1]) : "r"(addr))
#define MMA16816(c, a, b) \
    asm volatile("mma.sync.aligned.m16n8k16.row.col.f32.f16.f16.f32 " \
        "{%0,%1,%2,%3}, {%4,%5,%6,%7}, {%8,%9}, {%0,%1,%2,%3};" \
        : "+f"((c)[0]), "+f"((c)[1]), "+f"((c)[2]), "+f"((c)[3]) \
        : "r"((a)[0]), "r"((a)[1]), "r"((a)[2]), "r"((a)[3]), \
          "r"((b)[0]), "r"((b)[1]))

// ---------------------------------------------------------------------------
// prep_x: x_mod = x * s  ->  [n][h][w][c] fp16 hi/lo (tiled transpose)
// ---------------------------------------------------------------------------
__global__ __launch_bounds__(256) void prep_x_kernel(const float* __restrict__ x,
                                                     const float* __restrict__ s) {
    const int cb = blockIdx.x, h = blockIdx.y, n = blockIdx.z;
    __shared__ float tile[64][65];
    const int tid = threadIdx.x;
#pragma unroll
    for (int it = 0; it < 16; ++it) {
        int idx = it * 256 + tid;
        int c = idx >> 6, wq = idx & 63;
        float sv = s[n * CIN + cb * 64 + c];
        tile[c][wq] = x[(((size_t)n * CIN + cb * 64 + c) * HH + h) * WW + wq] * sv;
    }
    __syncthreads();
#pragma unroll
    for (int it = 0; it < 8; ++it) {
        int idx = it * 256 + tid;
        int cp = idx & 31, wq = idx >> 5;
        float v0 = tile[2 * cp][wq], v1 = tile[2 * cp + 1][wq];
        __half h0 = __float2half_rn(v0);
        __half h1 = __float2half_rn(v1);
        __half l0 = __float2half_rn(v0 - __half2float(h0));
        __half l1 = __float2half_rn(v1 - __half2float(h1));
        size_t off = (((size_t)n * HH + h) * WW + wq) * CIN + cb * 64 + 2 * cp;
        *(__half2*)(g_xhi + off) = __half2(h0, h1);
        *(__half2*)(g_xlo + off) = __half2(l0, l1);
    }
}

// ---------------------------------------------------------------------------
// prep_w: w -> [t][o][c] fp16 hi/lo + w2[c][o]
// ---------------------------------------------------------------------------
__global__ __launch_bounds__(256) void prep_w_kernel(const float* __restrict__ w) {
    int idx = blockIdx.x * 256 + threadIdx.x;
    if (idx >= CIN * COUT) return;
    int c = idx & 511, o = idx >> 9;
    const float* wp = w + ((size_t)o * CIN + c) * 9;
    float sum = 0.f;
#pragma unroll
    for (int t = 0; t < 9; ++t) {
        float v = wp[t];
        sum += v * v;
        __half hi = __float2half_rn(v);
        __half lo = __float2half_rn(v - __half2float(hi));
        size_t off = ((size_t)t * COUT + o) * CIN + c;
        g_whi[off] = hi;
        g_wlo[off] = lo;
    }
    g_w2[(size_t)c * COUT + o] = sum;
}

// ---------------------------------------------------------------------------
// d_kernel
// ---------------------------------------------------------------------------
__global__ void d_kernel(const float* __restrict__ s) {
    int n = blockIdx.y;
    int o = blockIdx.x * 128 + threadIdx.x;
    __shared__ float s2[CIN];
    for (int i = threadIdx.x; i < CIN; i += 128) {
        float v = s[n * CIN + i];
        s2[i] = v * v;
    }
    __syncthreads();
    float acc = 0.f;
#pragma unroll 8
    for (int c = 0; c < CIN; ++c) acc += s2[c] * g_w2[(size_t)c * COUT + o];
    g_d[n * COUT + o] = rsqrtf(acc + EPSF);
}

// ---------------------------------------------------------------------------
// main HMMA conv kernel — tap-stationary X region
// CTA = (128 outs, 256 pixels = 4 rows, n); 8 warps 4x2, warp = 64px x 64o
// X region: 6 rows x 66 cols (haloed) x 32c, hi+lo, double buffered
// B tile:   128 o x 32 c, hi+lo, triple buffered
// ---------------------------------------------------------------------------
#define XSL     80                     // bytes per pixel slot (32 halves + pad)
#define XROW    66                     // haloed width
#define XNSL    396                    // 6 * 66 slots
#define XH_B    (XNSL * XSL)           // 31680 (one matrix)
#define X_B     (2 * XH_B)             // 63360 hi+lo (one buffer)
#define AST     80                     // B: bytes per o-row
#define B_B     (128 * AST)            // 10240 (one matrix)
#define BSTG    (2 * B_B)              // 20480 hi+lo (one buffer)
#define SM_DYN  (1024 + 2 * X_B + 3 * BSTG)   // 189184

__global__ __launch_bounds__(256, 1)
void conv_mma_kernel(const float* __restrict__ noise,
                     const float* __restrict__ bias,
                     float* __restrict__ out) {
    extern __shared__ char smem[];
    float* dd = (float*)smem;          // 128 floats
    float* bb = dd + 128;              // 128 floats
    const uint32_t xsb = smem_to_u32(smem + 1024);
    const uint32_t bsb = xsb + 2 * X_B;

    const int tid = threadIdx.x;
    const int lid = tid & 31, wid = tid >> 5;
    const int wm = wid >> 1, wn = wid & 1;       // 4 x 2 warp grid; wm = image row
    const int o0 = blockIdx.x * 128;
    const int by = blockIdx.y;                   // image rows 4by .. 4by+3
    const int n  = blockIdx.z;

    if (tid < 128) {
        dd[tid] = g_d[n * COUT + o0 + tid];
        bb[tid] = bias[o0 + tid];
    }

    const __half* xh = g_xhi + (size_t)n * HH * WW * CIN;
    const __half* xl = g_xlo + (size_t)n * HH * WW * CIN;

    const int q0 = tid & 3;                      // 16B chunk
    const int pr = tid >> 2;                     // base row for B loads

    // ldmatrix per-thread base offsets
    const uint32_t aoff = (uint32_t)((wm * XROW + (lid & 15)) * XSL + (lid >> 4) * 16);
    const uint32_t boff = (uint32_t)((wn * 64 + (lid & 7)) * AST + ((lid >> 3) & 1) * 16);

    float C[4][8][4];
#pragma unroll
    for (int i = 0; i < 4; ++i)
#pragma unroll
        for (int j = 0; j < 8; ++j)
#pragma unroll
            for (int k = 0; k < 4; ++k) C[i][j][k] = 0.f;

    // ---- X region prefetch for c-block cb_ into buffer cb_&1 ----
#define PREF_X(cb_) do {                                                         \
    uint32_t xb_ = xsb + ((cb_) & 1) * X_B;                                      \
    _Pragma("unroll")                                                            \
    for (int it = 0; it < 7; ++it) {                                             \
        int idx = it * 256 + tid;                                                \
        if (idx < XNSL * 4) {                                                    \
            int slot = idx >> 2, q = idx & 3;                                    \
            int hl = slot / XROW, wl = slot - hl * XROW;                         \
            int h_ = 4 * by + hl - 1, w_ = wl - 1;                               \
            bool ok = (h_ >= 0) & (h_ < HH) & (w_ >= 0) & (w_ < WW);             \
            int gi = ok ? ((h_ * WW + w_) * CIN + (cb_) * 32 + q * 8) : 0;       \
            uint32_t d_ = xb_ + slot * XSL + q * 16;                             \
            cpa16(d_,        xh + gi, ok);                                       \
            cpa16(d_ + XH_B, xl + gi, ok);                                       \
        }                                                                        \
    }                                                                            \
} while (0)

    // ---- B prefetch for stage st (cb = st/9, tap = st%9) into buffer st%3 ----
#define PREF_B(st) do {                                                          \
    const int cb_ = (st) / 9, t_ = (st) - cb_ * 9;                               \
    uint32_t base_ = bsb + ((st) % 3) * BSTG;                                    \
    _Pragma("unroll")                                                            \
    for (int j = 0; j < 2; ++j) {                                                \
        int r = j * 64 + pr;                                                     \
        size_t wb = ((size_t)t_ * COUT + o0 + r) * CIN + cb_ * 32 + q0 * 8;      \
        uint32_t d_ = base_ + r * AST + q0 * 16;                                 \
        cpa16(d_,       g_whi + wb, true);                                       \
        cpa16(d_ + B_B, g_wlo + wb, true);                                       \
    }                                                                            \
} while (0)

    PREF_X(0);
    PREF_B(0); CP_COMMIT();
    PREF_B(1); CP_COMMIT();

#pragma unroll 1
    for (int s = 0; s < 144; ++s) {
        CP_WAIT1();
        __syncthreads();

        const int cb  = s / 9;
        const int tap = s - cb * 9;
        const int kh  = tap / 3, kw = tap - kh * 3;

        const uint32_t xb  = xsb + (cb & 1) * X_B;
        const uint32_t ahi = xb + aoff + (uint32_t)((kh * XROW + kw) * XSL);
        const uint32_t bhi = bsb + (s % 3) * BSTG;
        const uint32_t blo = bhi + B_B;

#pragma unroll
        for (int kc = 0; kc < 2; ++kc) {
            uint32_t bhf[8][2], blf[8][2];
#pragma unroll
            for (int nt = 0; nt < 8; ++nt) {
                uint32_t b = boff + nt * (8 * AST) + kc * 32;
                LDSM_X2(bhf[nt], bhi + b);
                LDSM_X2(blf[nt], blo + b);
            }
            uint32_t ahf[4][4], alf[4][4];
#pragma unroll
            for (int mt = 0; mt < 4; ++mt) {
                uint32_t a = ahi + mt * (16 * XSL) + kc * 32;
                LDSM_X4(ahf[mt], a);
                LDSM_X4(alf[mt], a + XH_B);
            }
#pragma unroll
            for (int mt = 0; mt < 4; ++mt)
#pragma unroll
                for (int nt = 0; nt < 8; ++nt) {
                    MMA16816(C[mt][nt], ahf[mt], bhf[nt]);
                    MMA16816(C[mt][nt], ahf[mt], blf[nt]);
                    MMA16816(C[mt][nt], alf[mt], bhf[nt]);
                }
        }

        if (s + 2 < 144) PREF_B(s + 2);
        if (tap == 0 && cb + 1 < 16) PREF_X(cb + 1);
        CP_COMMIT();
    }
#undef PREF_B
#undef PREF_X

    // ---- epilogue: demod, bias, noise, LeakyReLU ----
#pragma unroll
    for (int mt = 0; mt < 4; ++mt)
#pragma unroll
        for (int nt = 0; nt < 8; ++nt)
#pragma unroll
            for (int i = 0; i < 4; ++i) {
                int m = wm * 64 + mt * 16 + (lid >> 2) + (i >> 1) * 8;
                int o = wn * 64 + nt * 8 + (lid & 3) * 2 + (i & 1);
                int h = 4 * by + (m >> 6);
                int wq = m & 63;
                size_t oa = (((size_t)n * COUT + o0 + o) * HH + h) * WW + wq;
                float v = C[mt][nt][i] * dd[o] + bb[o] + noise[oa];
                out[oa] = (v >= 0.f) ? v : 0.2f * v;
            }
}

// ---------------------------------------------------------------------------
extern "C" void kernel_launch(void* const* d_in, const int* in_sizes, int n_in,
                              void* d_out, int out_size) {
    const float* x     = (const float*)d_in[0];
    const float* s     = (const float*)d_in[1];
    const float* noise = (const float*)d_in[2];
    const float* w     = (const float*)d_in[3];
    const float* b     = (const float*)d_in[4];
    float* out = (float*)d_out;

    cudaFuncSetAttribute(conv_mma_kernel,
                         cudaFuncAttributeMaxDynamicSharedMemorySize, SM_DYN);

    prep_x_kernel<<<dim3(8, 64, 16), 256>>>(x, s);
    prep_w_kernel<<<(CIN * COUT + 255) / 256, 256>>>(w);
    d_kernel<<<dim3(COUT / 128, NB), 128>>>(s);
    conv_mma_kernel<<<dim3(COUT / 128, HH / 4, NB), 256, SM_DYN>>>(noise, b, out);
}

// round 8
// speedup vs baseline: 9.7565x; 1.3686x over previous
#include <cuda_runtime.h>
#include <cuda_fp16.h>
#include <cstdint>

#define HH    64
#define WW    64
#define CIN   512
#define COUT  512
#define NB    16
#define EPSF  1e-8f

// ---------------- scratch (__device__ globals) -----------------------------
__device__ __half g_xhi[(size_t)NB * HH * WW * CIN];   // [n][h][w][c]
__device__ __half g_whi[(size_t)9 * COUT * CIN];       // [t][o][c]
__device__ __half g_wlo[(size_t)9 * COUT * CIN];
__device__ float  g_w2 [(size_t)CIN * COUT];           // [c][o]
__device__ float  g_d  [(size_t)NB * COUT];            // [n][o]

// ---------------- helpers --------------------------------------------------
__device__ __forceinline__ uint32_t smem_to_u32(const void* p) {
    uint32_t a;
    asm("{ .reg .u64 t; cvta.to.shared.u64 t, %1; cvt.u32.u64 %0, t; }"
        : "=r"(a) : "l"(p));
    return a;
}
__device__ __forceinline__ void cpa16(uint32_t dst, const void* src, bool ok) {
    asm volatile("cp.async.cg.shared.global [%0], [%1], 16, %2;"
                 :: "r"(dst), "l"(src), "r"(ok ? 16u : 0u) : "memory");
}
#define CP_COMMIT() asm volatile("cp.async.commit_group;" ::: "memory")
#define CP_WAIT1()  asm volatile("cp.async.wait_group 1;" ::: "memory")

#define LDSM_X4(r, addr) \
    asm volatile("ldmatrix.sync.aligned.m8n8.x4.shared.b16 {%0,%1,%2,%3}, [%4];" \
        : "=r"((r)[0]), "=r"((r)[1]), "=r"((r)[2]), "=r"((r)[3]) : "r"(addr))
#define LDSM_X2(r, addr) \
    asm volatile("ldmatrix.sync.aligned.m8n8.x2.shared.b16 {%0,%1}, [%2];" \
        : "=r"((r)[0]), "=r"((r)[1]) : "r"(addr))
#define MMA16816(c, a, b) \
    asm volatile("mma.sync.aligned.m16n8k16.row.col.f32.f16.f16.f32 " \
        "{%0,%1,%2,%3}, {%4,%5,%6,%7}, {%8,%9}, {%0,%1,%2,%3};" \
        : "+f"((c)[0]), "+f"((c)[1]), "+f"((c)[2]), "+f"((c)[3]) \
        : "r"((a)[0]), "r"((a)[1]), "r"((a)[2]), "r"((a)[3]), \
          "r"((b)[0]), "r"((b)[1]))

// ---------------------------------------------------------------------------
// prep_x: x_mod = x * s  ->  [n][h][w][c] fp16 (hi only; tiled transpose)
// ---------------------------------------------------------------------------
__global__ __launch_bounds__(256) void prep_x_kernel(const float* __restrict__ x,
                                                     const float* __restrict__ s) {
    const int cb = blockIdx.x, h = blockIdx.y, n = blockIdx.z;
    __shared__ float tile[64][65];
    const int tid = threadIdx.x;
#pragma unroll
    for (int it = 0; it < 16; ++it) {
        int idx = it * 256 + tid;
        int c = idx >> 6, wq = idx & 63;
        float sv = s[n * CIN + cb * 64 + c];
        tile[c][wq] = x[(((size_t)n * CIN + cb * 64 + c) * HH + h) * WW + wq] * sv;
    }
    __syncthreads();
#pragma unroll
    for (int it = 0; it < 8; ++it) {
        int idx = it * 256 + tid;
        int cp = idx & 31, wq = idx >> 5;
        __half h0 = __float2half_rn(tile[2 * cp][wq]);
        __half h1 = __float2half_rn(tile[2 * cp + 1][wq]);
        size_t off = (((size_t)n * HH + h) * WW + wq) * CIN + cb * 64 + 2 * cp;
        *(__half2*)(g_xhi + off) = __half2(h0, h1);
    }
}

// ---------------------------------------------------------------------------
// prep_w: w -> [t][o][c] fp16 hi/lo + w2[c][o]
// ---------------------------------------------------------------------------
__global__ __launch_bounds__(256) void prep_w_kernel(const float* __restrict__ w) {
    int idx = blockIdx.x * 256 + threadIdx.x;
    if (idx >= CIN * COUT) return;
    int c = idx & 511, o = idx >> 9;
    const float* wp = w + ((size_t)o * CIN + c) * 9;
    float sum = 0.f;
#pragma unroll
    for (int t = 0; t < 9; ++t) {
        float v = wp[t];
        sum += v * v;
        __half hi = __float2half_rn(v);
        __half lo = __float2half_rn(v - __half2float(hi));
        size_t off = ((size_t)t * COUT + o) * CIN + c;
        g_whi[off] = hi;
        g_wlo[off] = lo;
    }
    g_w2[(size_t)c * COUT + o] = sum;
}

// ---------------------------------------------------------------------------
// d_kernel
// ---------------------------------------------------------------------------
__global__ void d_kernel(const float* __restrict__ s) {
    int n = blockIdx.y;
    int o = blockIdx.x * 128 + threadIdx.x;
    __shared__ float s2[CIN];
    for (int i = threadIdx.x; i < CIN; i += 128) {
        float v = s[n * CIN + i];
        s2[i] = v * v;
    }
    __syncthreads();
    float acc = 0.f;
#pragma unroll 8
    for (int c = 0; c < CIN; ++c) acc += s2[c] * g_w2[(size_t)c * COUT + o];
    g_d[n * COUT + o] = rsqrtf(acc + EPSF);
}

// ---------------------------------------------------------------------------
// main HMMA conv kernel — tap-stationary X, 2-term split (xhi*(whi+wlo))
// CTA = (128 outs, 256 pixels = 4 rows, n); 8 warps 2x4, warp = 128px x 32o
// X region: 6 rows x 66 cols (haloed) x 32c (hi only), double buffered
// B tile:   128 o x 32 c, hi+lo, triple buffered
// ---------------------------------------------------------------------------
#define XSL     80                     // bytes per pixel slot (32 halves + pad)
#define XROW    66                     // haloed width
#define XNSL    396                    // 6 * 66 slots
#define X_B     (XNSL * XSL)           // 31680 (one buffer, hi only)
#define AST     80                     // B: bytes per o-row
#define B_B     (128 * AST)            // 10240 (one matrix)
#define BSTG    (2 * B_B)              // 20480 hi+lo (one buffer)
#define SM_DYN  (1024 + 2 * X_B + 3 * BSTG)   // 125824

__global__ __launch_bounds__(256, 1)
void conv_mma_kernel(const float* __restrict__ noise,
                     const float* __restrict__ bias,
                     float* __restrict__ out) {
    extern __shared__ char smem[];
    float* dd = (float*)smem;          // 128 floats
    float* bb = dd + 128;              // 128 floats
    const uint32_t xsb = smem_to_u32(smem + 1024);
    const uint32_t bsb = xsb + 2 * X_B;

    const int tid = threadIdx.x;
    const int lid = tid & 31, wid = tid >> 5;
    const int wm = wid >> 2, wn = wid & 3;       // 2 x 4 warp grid
    const int o0 = blockIdx.x * 128;
    const int by = blockIdx.y;                   // image rows 4by .. 4by+3
    const int n  = blockIdx.z;

    if (tid < 128) {
        dd[tid] = g_d[n * COUT + o0 + tid];
        bb[tid] = bias[o0 + tid];
    }

    const __half* xh = g_xhi + (size_t)n * HH * WW * CIN;

    const int q0 = tid & 3;                      // 16B chunk
    const int pr = tid >> 2;                     // base row for B loads

    // ldmatrix per-thread base offsets
    // A: warp wm covers image rows 2wm, 2wm+1 (local); mt>>2 selects row,
    //    mt&3 selects 16-col block.
    const uint32_t aoff = (uint32_t)(((wm * 2) * XROW + (lid & 15)) * XSL
                                     + (lid >> 4) * 16);
    const uint32_t boff = (uint32_t)((wn * 32 + (lid & 7)) * AST + ((lid >> 3) & 1) * 16);

    float C[8][4][4];
#pragma unroll
    for (int i = 0; i < 8; ++i)
#pragma unroll
        for (int j = 0; j < 4; ++j)
#pragma unroll
            for (int k = 0; k < 4; ++k) C[i][j][k] = 0.f;

    // ---- X region prefetch for c-block cb_ into buffer cb_&1 (hi only) ----
#define PREF_X(cb_) do {                                                         \
    uint32_t xb_ = xsb + ((cb_) & 1) * X_B;                                      \
    _Pragma("unroll")                                                            \
    for (int it = 0; it < 7; ++it) {                                             \
        int idx = it * 256 + tid;                                                \
        if (idx < XNSL * 4) {                                                    \
            int slot = idx >> 2, q = idx & 3;                                    \
            int hl = slot / XROW, wl = slot - hl * XROW;                         \
            int h_ = 4 * by + hl - 1, w_ = wl - 1;                               \
            bool ok = (h_ >= 0) & (h_ < HH) & (w_ >= 0) & (w_ < WW);             \
            int gi = ok ? ((h_ * WW + w_) * CIN + (cb_) * 32 + q * 8) : 0;       \
            cpa16(xb_ + slot * XSL + q * 16, xh + gi, ok);                       \
        }                                                                        \
    }                                                                            \
} while (0)

    // ---- B prefetch for stage st (cb = st/9, tap = st%9) into buffer st%3 ----
#define PREF_B(st) do {                                                          \
    const int cb_ = (st) / 9, t_ = (st) - cb_ * 9;                               \
    uint32_t base_ = bsb + ((st) % 3) * BSTG;                                    \
    _Pragma("unroll")                                                            \
    for (int j = 0; j < 2; ++j) {                                                \
        int r = j * 64 + pr;                                                     \
        size_t wb = ((size_t)t_ * COUT + o0 + r) * CIN + cb_ * 32 + q0 * 8;      \
        uint32_t d_ = base_ + r * AST + q0 * 16;                                 \
        cpa16(d_,       g_whi + wb, true);                                       \
        cpa16(d_ + B_B, g_wlo + wb, true);                                       \
    }                                                                            \
} while (0)

    PREF_X(0);
    PREF_B(0); CP_COMMIT();
    PREF_B(1); CP_COMMIT();

#pragma unroll 1
    for (int s = 0; s < 144; ++s) {
        CP_WAIT1();
        __syncthreads();

        const int cb  = s / 9;
        const int tap = s - cb * 9;
        const int kh  = tap / 3, kw = tap - kh * 3;

        const uint32_t xb  = xsb + (cb & 1) * X_B;
        const uint32_t abase = xb + aoff + (uint32_t)((kh * XROW + kw) * XSL);
        const uint32_t bhi = bsb + (s % 3) * BSTG;
        const uint32_t blo = bhi + B_B;

#pragma unroll
        for (int kc = 0; kc < 2; ++kc) {
            uint32_t bhf[4][2], blf[4][2];
#pragma unroll
            for (int nt = 0; nt < 4; ++nt) {
                uint32_t b = boff + nt * (8 * AST) + kc * 32;
                LDSM_X2(bhf[nt], bhi + b);
                LDSM_X2(blf[nt], blo + b);
            }
            uint32_t ahf[8][4];
#pragma unroll
            for (int mt = 0; mt < 8; ++mt) {
                uint32_t a = abase + ((mt >> 2) * XROW + (mt & 3) * 16) * XSL
                             + kc * 32;
                LDSM_X4(ahf[mt], a);
            }
#pragma unroll
            for (int mt = 0; mt < 8; ++mt)
#pragma unroll
                for (int nt = 0; nt < 4; ++nt) {
                    MMA16816(C[mt][nt], ahf[mt], bhf[nt]);
                    MMA16816(C[mt][nt], ahf[mt], blf[nt]);
                }
        }

        if (s + 2 < 144) PREF_B(s + 2);
        if (tap == 0 && cb + 1 < 16) PREF_X(cb + 1);
        CP_COMMIT();
    }
#undef PREF_B
#undef PREF_X

    // ---- epilogue: demod, bias, noise, LeakyReLU ----
#pragma unroll
    for (int mt = 0; mt < 8; ++mt)
#pragma unroll
        for (int nt = 0; nt < 4; ++nt)
#pragma unroll
            for (int i = 0; i < 4; ++i) {
                int h  = 4 * by + wm * 2 + (mt >> 2);
                int wq = (mt & 3) * 16 + (lid >> 2) + (i >> 1) * 8;
                int o  = wn * 32 + nt * 8 + (lid & 3) * 2 + (i & 1);
                size_t oa = (((size_t)n * COUT + o0 + o) * HH + h) * WW + wq;
                float v = C[mt][nt][i] * dd[o] + bb[o] + noise[oa];
                out[oa] = (v >= 0.f) ? v : 0.2f * v;
            }
}

// ---------------------------------------------------------------------------
extern "C" void kernel_launch(void* const* d_in, const int* in_sizes, int n_in,
                              void* d_out, int out_size) {
    const float* x     = (const float*)d_in[0];
    const float* s     = (const float*)d_in[1];
    const float* noise = (const float*)d_in[2];
    const float* w     = (const float*)d_in[3];
    const float* b     = (const float*)d_in[4];
    float* out = (float*)d_out;

    cudaFuncSetAttribute(conv_mma_kernel,
                         cudaFuncAttributeMaxDynamicSharedMemorySize, SM_DYN);

    prep_x_kernel<<<dim3(8, 64, 16), 256>>>(x, s);
    prep_w_kernel<<<(CIN * COUT + 255) / 256, 256>>>(w);
    d_kernel<<<dim3(COUT / 128, NB), 128>>>(s);
    conv_mma_kernel<<<dim3(COUT / 128, HH / 4, NB), 256, SM_DYN>>>(noise, b, out);
}

// round 9
// speedup vs baseline: 16.1647x; 1.6568x over previous
#include <cuda_runtime.h>
#include <cuda_fp16.h>
#include <cstdint>

#define HH    64
#define WW    64
#define CIN   512
#define COUT  512
#define NB    16
#define EPSF  1e-8f

// ---------------- scratch (__device__ globals) -----------------------------
__device__ __half g_xhi[(size_t)NB * HH * WW * CIN];   // [n][h][w][c]
__device__ __half g_whi[(size_t)9 * COUT * CIN];       // [t][o][c]
__device__ float  g_w2 [(size_t)CIN * COUT];           // [c][o]
__device__ float  g_d  [(size_t)NB * COUT];            // [n][o]

// ---------------- helpers --------------------------------------------------
__device__ __forceinline__ uint32_t smem_to_u32(const void* p) {
    uint32_t a;
    asm("{ .reg .u64 t; cvta.to.shared.u64 t, %1; cvt.u32.u64 %0, t; }"
        : "=r"(a) : "l"(p));
    return a;
}
__device__ __forceinline__ void cpa16(uint32_t dst, const void* src, bool ok) {
    asm volatile("cp.async.cg.shared.global [%0], [%1], 16, %2;"
                 :: "r"(dst), "l"(src), "r"(ok ? 16u : 0u) : "memory");
}
#define CP_COMMIT() asm volatile("cp.async.commit_group;" ::: "memory")
#define CP_WAIT1()  asm volatile("cp.async.wait_group 1;" ::: "memory")

#define LDSM_X4(r, addr) \
    asm volatile("ldmatrix.sync.aligned.m8n8.x4.shared.b16 {%0,%1,%2,%3}, [%4];" \
        : "=r"((r)[0]), "=r"((r)[1]), "=r"((r)[2]), "=r"((r)[3]) : "r"(addr))
#define LDSM_X2(r, addr) \
    asm volatile("ldmatrix.sync.aligned.m8n8.x2.shared.b16 {%0,%1}, [%2];" \
        : "=r"((r)[0]), "=r"((r)[1]) : "r"(addr))
#define MMA16816(c, a, b) \
    asm volatile("mma.sync.aligned.m16n8k16.row.col.f32.f16.f16.f32 " \
        "{%0,%1,%2,%3}, {%4,%5,%6,%7}, {%8,%9}, {%0,%1,%2,%3};" \
        : "+f"((c)[0]), "+f"((c)[1]), "+f"((c)[2]), "+f"((c)[3]) \
        : "r"((a)[0]), "r"((a)[1]), "r"((a)[2]), "r"((a)[3]), \
          "r"((b)[0]), "r"((b)[1]))

// ---------------------------------------------------------------------------
// prep_x: x_mod = x * s  ->  [n][h][w][c] fp16 (tiled transpose)
// ---------------------------------------------------------------------------
__global__ __launch_bounds__(256) void prep_x_kernel(const float* __restrict__ x,
                                                     const float* __restrict__ s) {
    const int cb = blockIdx.x, h = blockIdx.y, n = blockIdx.z;
    __shared__ float tile[64][65];
    const int tid = threadIdx.x;
#pragma unroll
    for (int it = 0; it < 16; ++it) {
        int idx = it * 256 + tid;
        int c = idx >> 6, wq = idx & 63;
        float sv = s[n * CIN + cb * 64 + c];
        tile[c][wq] = x[(((size_t)n * CIN + cb * 64 + c) * HH + h) * WW + wq] * sv;
    }
    __syncthreads();
#pragma unroll
    for (int it = 0; it < 8; ++it) {
        int idx = it * 256 + tid;
        int cp = idx & 31, wq = idx >> 5;
        __half h0 = __float2half_rn(tile[2 * cp][wq]);
        __half h1 = __float2half_rn(tile[2 * cp + 1][wq]);
        size_t off = (((size_t)n * HH + h) * WW + wq) * CIN + cb * 64 + 2 * cp;
        *(__half2*)(g_xhi + off) = __half2(h0, h1);
    }
}

// ---------------------------------------------------------------------------
// prep_w: w -> [t][o][c] fp16 + w2[c][o]
// ---------------------------------------------------------------------------
__global__ __launch_bounds__(256) void prep_w_kernel(const float* __restrict__ w) {
    int idx = blockIdx.x * 256 + threadIdx.x;
    if (idx >= CIN * COUT) return;
    int c = idx & 511, o = idx >> 9;
    const float* wp = w + ((size_t)o * CIN + c) * 9;
    float sum = 0.f;
#pragma unroll
    for (int t = 0; t < 9; ++t) {
        float v = wp[t];
        sum += v * v;
        g_whi[((size_t)t * COUT + o) * CIN + c] = __float2half_rn(v);
    }
    g_w2[(size_t)c * COUT + o] = sum;
}

// ---------------------------------------------------------------------------
// d_kernel
// ---------------------------------------------------------------------------
__global__ void d_kernel(const float* __restrict__ s) {
    int n = blockIdx.y;
    int o = blockIdx.x * 128 + threadIdx.x;
    __shared__ float s2[CIN];
    for (int i = threadIdx.x; i < CIN; i += 128) {
        float v = s[n * CIN + i];
        s2[i] = v * v;
    }
    __syncthreads();
    float acc = 0.f;
#pragma unroll 8
    for (int c = 0; c < CIN; ++c) acc += s2[c] * g_w2[(size_t)c * COUT + o];
    g_d[n * COUT + o] = rsqrtf(acc + EPSF);
}

// ---------------------------------------------------------------------------
// main HMMA conv kernel — single-pass fp16, tap-stationary X, 3 taps/stage
// CTA = (128 outs, 256 pixels = 4 rows, n); 8 warps 2x4, warp = 128px x 32o
// Stage = (cb, kh): covers kw = 0..2.  48 stages total.
// X region: 6 rows x 66 cols (haloed) x 32c, double buffered (per cb)
// B buffer: 3 taps x 128 o x 32 c, double buffered (per stage)
// ---------------------------------------------------------------------------
#define XSL     80                     // bytes per pixel slot (32 halves + pad)
#define XROW    66                     // haloed width
#define XNSL    396                    // 6 * 66 slots
#define X_B     (XNSL * XSL)           // 31680 (one buffer)
#define AST     80                     // B: bytes per o-row
#define B_B     (128 * AST)            // 10240 (one tap)
#define BST     (3 * B_B)              // 30720 (one stage buffer)
#define SM_DYN  (1024 + 2 * X_B + 2 * BST)   // 125824

__global__ __launch_bounds__(256, 1)
void conv_mma_kernel(const float* __restrict__ noise,
                     const float* __restrict__ bias,
                     float* __restrict__ out) {
    extern __shared__ char smem[];
    float* dd = (float*)smem;          // 128 floats
    float* bb = dd + 128;              // 128 floats
    const uint32_t xsb = smem_to_u32(smem + 1024);
    const uint32_t bsb = xsb + 2 * X_B;

    const int tid = threadIdx.x;
    const int lid = tid & 31, wid = tid >> 5;
    const int wm = wid >> 2, wn = wid & 3;       // 2 x 4 warp grid
    const int o0 = blockIdx.x * 128;
    const int by = blockIdx.y;                   // image rows 4by .. 4by+3
    const int n  = blockIdx.z;

    if (tid < 128) {
        dd[tid] = g_d[n * COUT + o0 + tid];
        bb[tid] = bias[o0 + tid];
    }

    const __half* xh = g_xhi + (size_t)n * HH * WW * CIN;

    const int q0 = tid & 3;                      // 16B chunk
    const int pr = tid >> 2;                     // base row for B loads

    // ldmatrix per-thread base offsets
    const uint32_t aoff = (uint32_t)(((wm * 2) * XROW + (lid & 15)) * XSL
                                     + (lid >> 4) * 16);
    const uint32_t boff = (uint32_t)((wn * 32 + (lid & 7)) * AST + ((lid >> 3) & 1) * 16);

    float C[8][4][4];
#pragma unroll
    for (int i = 0; i < 8; ++i)
#pragma unroll
        for (int j = 0; j < 4; ++j)
#pragma unroll
            for (int k = 0; k < 4; ++k) C[i][j][k] = 0.f;

    // ---- X region prefetch for c-block cb_ into buffer cb_&1 ----
#define PREF_X(cb_) do {                                                         \
    uint32_t xb_ = xsb + ((cb_) & 1) * X_B;                                      \
    _Pragma("unroll")                                                            \
    for (int it = 0; it < 7; ++it) {                                             \
        int idx = it * 256 + tid;                                                \
        if (idx < XNSL * 4) {                                                    \
            int slot = idx >> 2, q = idx & 3;                                    \
            int hl = slot / XROW, wl = slot - hl * XROW;                         \
            int h_ = 4 * by + hl - 1, w_ = wl - 1;                               \
            bool ok = (h_ >= 0) & (h_ < HH) & (w_ >= 0) & (w_ < WW);             \
            int gi = ok ? ((h_ * WW + w_) * CIN + (cb_) * 32 + q * 8) : 0;       \
            cpa16(xb_ + slot * XSL + q * 16, xh + gi, ok);                       \
        }                                                                        \
    }                                                                            \
} while (0)

    // ---- B prefetch for stage st (cb = st/3, kh = st%3): 3 kw taps ----
#define PREF_B(st) do {                                                          \
    const int cb_ = (st) / 3, kh_ = (st) - cb_ * 3;                              \
    uint32_t base_ = bsb + ((st) & 1) * BST;                                     \
    _Pragma("unroll")                                                            \
    for (int kw_ = 0; kw_ < 3; ++kw_) {                                          \
        const int t_ = kh_ * 3 + kw_;                                            \
        _Pragma("unroll")                                                        \
        for (int j = 0; j < 2; ++j) {                                            \
            int r = j * 64 + pr;                                                 \
            size_t wb = ((size_t)t_ * COUT + o0 + r) * CIN + cb_ * 32 + q0 * 8;  \
            cpa16(base_ + kw_ * B_B + r * AST + q0 * 16, g_whi + wb, true);      \
        }                                                                        \
    }                                                                            \
} while (0)

    PREF_X(0);
    PREF_B(0); CP_COMMIT();

#pragma unroll 1
    for (int s = 0; s < 48; ++s) {
        const int cb = s / 3;
        const int kh = s - cb * 3;

        if (s + 1 < 48) PREF_B(s + 1);
        if (kh == 0 && cb + 1 < 16) PREF_X(cb + 1);
        CP_COMMIT();
        CP_WAIT1();
        __syncthreads();

        const uint32_t xb    = xsb + (cb & 1) * X_B;
        const uint32_t abase = xb + aoff + (uint32_t)(kh * XROW * XSL);
        const uint32_t bbase = bsb + (s & 1) * BST + boff;

#pragma unroll
        for (int kw = 0; kw < 3; ++kw) {
#pragma unroll
            for (int kc = 0; kc < 2; ++kc) {
                uint32_t bhf[4][2];
#pragma unroll
                for (int nt = 0; nt < 4; ++nt)
                    LDSM_X2(bhf[nt], bbase + kw * B_B + nt * (8 * AST) + kc * 32);
                uint32_t ahf[8][4];
#pragma unroll
                for (int mt = 0; mt < 8; ++mt)
                    LDSM_X4(ahf[mt], abase + kw * XSL
                            + ((mt >> 2) * XROW + (mt & 3) * 16) * XSL + kc * 32);
#pragma unroll
                for (int mt = 0; mt < 8; ++mt)
#pragma unroll
                    for (int nt = 0; nt < 4; ++nt)
                        MMA16816(C[mt][nt], ahf[mt], bhf[nt]);
            }
        }
        __syncthreads();
    }
#undef PREF_B
#undef PREF_X

    // ---- epilogue: demod, bias, noise, LeakyReLU ----
#pragma unroll
    for (int mt = 0; mt < 8; ++mt)
#pragma unroll
        for (int nt = 0; nt < 4; ++nt)
#pragma unroll
            for (int i = 0; i < 4; ++i) {
                int h  = 4 * by + wm * 2 + (mt >> 2);
                int wq = (mt & 3) * 16 + (lid >> 2) + (i >> 1) * 8;
                int o  = wn * 32 + nt * 8 + (lid & 3) * 2 + (i & 1);
                size_t oa = (((size_t)n * COUT + o0 + o) * HH + h) * WW + wq;
                float v = C[mt][nt][i] * dd[o] + bb[o] + noise[oa];
                out[oa] = (v >= 0.f) ? v : 0.2f * v;
            }
}

// ---------------------------------------------------------------------------
extern "C" void kernel_launch(void* const* d_in, const int* in_sizes, int n_in,
                              void* d_out, int out_size) {
    const float* x     = (const float*)d_in[0];
    const float* s     = (const float*)d_in[1];
    const float* noise = (const float*)d_in[2];
    const float* w     = (const float*)d_in[3];
    const float* b     = (const float*)d_in[4];
    float* out = (float*)d_out;

    cudaFuncSetAttribute(conv_mma_kernel,
                         cudaFuncAttributeMaxDynamicSharedMemorySize, SM_DYN);

    prep_x_kernel<<<dim3(8, 64, 16), 256>>>(x, s);
    prep_w_kernel<<<(CIN * COUT + 255) / 256, 256>>>(w);
    d_kernel<<<dim3(COUT / 128, NB), 128>>>(s);
    conv_mma_kernel<<<dim3(COUT / 128, HH / 4, NB), 256, SM_DYN>>>(noise, b, out);
}

// round 11
// speedup vs baseline: 16.5229x; 1.0222x over previous
#include <cuda_runtime.h>
#include <cuda_fp16.h>
#include <cstdint>

#define HH    64
#define WW    64
#define CIN   512
#define COUT  512
#define NB    16
#define EPSF  1e-8f

// ---------------- scratch (__device__ globals) -----------------------------
__device__ __half g_xhi[(size_t)NB * HH * WW * CIN];   // [n][h][w][c]
__device__ __half g_whi[(size_t)9 * COUT * CIN];       // [t][o][c]
__device__ float  g_w2 [(size_t)CIN * COUT];           // [c][o]
__device__ float  g_d  [(size_t)NB * COUT];            // [n][o]

// ---------------- helpers --------------------------------------------------
__device__ __forceinline__ uint32_t smem_to_u32(const void* p) {
    uint32_t a;
    asm("{ .reg .u64 t; cvta.to.shared.u64 t, %1; cvt.u32.u64 %0, t; }"
        : "=r"(a) : "l"(p));
    return a;
}
__device__ __forceinline__ void cpa16(uint32_t dst, const void* src, bool ok) {
    asm volatile("cp.async.cg.shared.global [%0], [%1], 16, %2;"
                 :: "r"(dst), "l"(src), "r"(ok ? 16u : 0u) : "memory");
}
#define CP_COMMIT() asm volatile("cp.async.commit_group;" ::: "memory")
#define CP_WAIT1()  asm volatile("cp.async.wait_group 1;" ::: "memory")

#define LDSM_X4(r, addr) \
    asm volatile("ldmatrix.sync.aligned.m8n8.x4.shared.b16 {%0,%1,%2,%3}, [%4];" \
        : "=r"((r)[0]), "=r"((r)[1]), "=r"((r)[2]), "=r"((r)[3]) : "r"(addr))
#define LDSM_X2(r, addr) \
    asm volatile("ldmatrix.sync.aligned.m8n8.x2.shared.b16 {%0,%1}, [%2];" \
        : "=r"((r)[0]), "=r"((r)[1]) : "r"(addr))
#define MMA16816(c, a, b) \
    asm volatile("mma.sync.aligned.m16n8k16.row.col.f32.f16.f16.f32 " \
        "{%0,%1,%2,%3}, {%4,%5,%6,%7}, {%8,%9}, {%0,%1,%2,%3};" \
        : "+f"((c)[0]), "+f"((c)[1]), "+f"((c)[2]), "+f"((c)[3]) \
        : "r"((a)[0]), "r"((a)[1]), "r"((a)[2]), "r"((a)[3]), \
          "r"((b)[0]), "r"((b)[1]))

// ---------------------------------------------------------------------------
// prep_x: x_mod = x * s  ->  [n][h][w][c] fp16 (tiled transpose)
// ---------------------------------------------------------------------------
__global__ __launch_bounds__(256) void prep_x_kernel(const float* __restrict__ x,
                                                     const float* __restrict__ s) {
    const int cb = blockIdx.x, h = blockIdx.y, n = blockIdx.z;
    __shared__ float tile[64][65];
    const int tid = threadIdx.x;
#pragma unroll
    for (int it = 0; it < 16; ++it) {
        int idx = it * 256 + tid;
        int c = idx >> 6, wq = idx & 63;
        float sv = s[n * CIN + cb * 64 + c];
        tile[c][wq] = x[(((size_t)n * CIN + cb * 64 + c) * HH + h) * WW + wq] * sv;
    }
    __syncthreads();
#pragma unroll
    for (int it = 0; it < 8; ++it) {
        int idx = it * 256 + tid;
        int cp = idx & 31, wq = idx >> 5;
        __half h0 = __float2half_rn(tile[2 * cp][wq]);
        __half h1 = __float2half_rn(tile[2 * cp + 1][wq]);
        size_t off = (((size_t)n * HH + h) * WW + wq) * CIN + cb * 64 + 2 * cp;
        *(__half2*)(g_xhi + off) = __half2(h0, h1);
    }
}

// ---------------------------------------------------------------------------
// prep_w: w -> [t][o][c] fp16 + w2[c][o]
// ---------------------------------------------------------------------------
__global__ __launch_bounds__(256) void prep_w_kernel(const float* __restrict__ w) {
    int idx = blockIdx.x * 256 + threadIdx.x;
    if (idx >= CIN * COUT) return;
    int c = idx & 511, o = idx >> 9;
    const float* wp = w + ((size_t)o * CIN + c) * 9;
    float sum = 0.f;
#pragma unroll
    for (int t = 0; t < 9; ++t) {
        float v = wp[t];
        sum += v * v;
        g_whi[((size_t)t * COUT + o) * CIN + c] = __float2half_rn(v);
    }
    g_w2[(size_t)c * COUT + o] = sum;
}

// ---------------------------------------------------------------------------
// d_kernel
// ---------------------------------------------------------------------------
__global__ void d_kernel(const float* __restrict__ s) {
    int n = blockIdx.y;
    int o = blockIdx.x * 128 + threadIdx.x;
    __shared__ float s2[CIN];
    for (int i = threadIdx.x; i < CIN; i += 128) {
        float v = s[n * CIN + i];
        s2[i] = v * v;
    }
    __syncthreads();
    float acc = 0.f;
#pragma unroll 8
    for (int c = 0; c < CIN; ++c) acc += s2[c] * g_w2[(size_t)c * COUT + o];
    g_d[n * COUT + o] = rsqrtf(acc + EPSF);
}

// ---------------------------------------------------------------------------
// main HMMA conv kernel — single-pass fp16, tap-stationary X, 3 taps/stage
// CTA = (128 outs, 256 pixels = 4 rows, n); 16 warps 4x4, warp = 64px x 32o
// (warp wm handles image row 4by+wm)
// X region: 6 rows x 66 cols (haloed) x 32c, double buffered (per cb)
// B buffer: 3 taps x 128 o x 32 c, double buffered (per stage)
// ---------------------------------------------------------------------------
#define NT      512
#define XSL     80                     // bytes per pixel slot (32 halves + pad)
#define XROW    66                     // haloed width
#define XNSL    396                    // 6 * 66 slots
#define X_B     (XNSL * XSL)           // 31680 (one buffer)
#define AST     80                     // B: bytes per o-row
#define B_B     (128 * AST)            // 10240 (one tap)
#define BST     (3 * B_B)              // 30720 (one stage buffer)
#define SM_DYN  (1024 + 2 * X_B + 2 * BST)   // 125824

__global__ __launch_bounds__(NT, 1)
void conv_mma_kernel(const float* __restrict__ noise,
                     const float* __restrict__ bias,
                     float* __restrict__ out) {
    extern __shared__ char smem[];
    float* dd = (float*)smem;          // 128 floats
    float* bb = dd + 128;              // 128 floats
    const uint32_t xsb = smem_to_u32(smem + 1024);
    const uint32_t bsb = xsb + 2 * X_B;

    const int tid = threadIdx.x;
    const int lid = tid & 31, wid = tid >> 5;
    const int wm = wid >> 2, wn = wid & 3;       // 4 x 4 warp grid
    const int o0 = blockIdx.x * 128;
    const int by = blockIdx.y;                   // image rows 4by .. 4by+3
    const int n  = blockIdx.z;

    if (tid < 128) {
        dd[tid] = g_d[n * COUT + o0 + tid];
        bb[tid] = bias[o0 + tid];
    }

    const __half* xh = g_xhi + (size_t)n * HH * WW * CIN;

    // ldmatrix per-thread base offsets (warp wm = local image row wm)
    const uint32_t aoff = (uint32_t)((wm * XROW + (lid & 15)) * XSL
                                     + (lid >> 4) * 16);
    const uint32_t boff = (uint32_t)((wn * 32 + (lid & 7)) * AST + ((lid >> 3) & 1) * 16);

    float C[4][4][4];
#pragma unroll
    for (int i = 0; i < 4; ++i)
#pragma unroll
        for (int j = 0; j < 4; ++j)
#pragma unroll
            for (int k = 0; k < 4; ++k) C[i][j][k] = 0.f;

    // ---- X region prefetch for c-block cb_ into buffer cb_&1 ----
    // 396 slots x 4 chunks = 1584 cp.async over 512 threads
#define PREF_X(cb_) do {                                                         \
    uint32_t xb_ = xsb + ((cb_) & 1) * X_B;                                      \
    _Pragma("unroll")                                                            \
    for (int it = 0; it < 4; ++it) {                                             \
        int idx = it * NT + tid;                                                 \
        if (idx < XNSL * 4) {                                                    \
            int slot = idx >> 2, q = idx & 3;                                    \
            int hl = slot / XROW, wl = slot - hl * XROW;                         \
            int h_ = 4 * by + hl - 1, w_ = wl - 1;                               \
            bool ok = (h_ >= 0) & (h_ < HH) & (w_ >= 0) & (w_ < WW);             \
            int gi = ok ? ((h_ * WW + w_) * CIN + (cb_) * 32 + q * 8) : 0;       \
            cpa16(xb_ + slot * XSL + q * 16, xh + gi, ok);                       \
        }                                                                        \
    }                                                                            \
} while (0)

    // ---- B prefetch for stage st (cb = st/3, kh = st%3): 3 kw taps ----
    // 3 taps x 128 rows x 4 chunks = 1536 cp.async over 512 threads
#define PREF_B(st) do {                                                          \
    const int cb_ = (st) / 3, kh_ = (st) - cb_ * 3;                              \
    uint32_t base_ = bsb + ((st) & 1) * BST;                                     \
    _Pragma("unroll")                                                            \
    for (int it = 0; it < 3; ++it) {                                             \
        int idx = it * NT + tid;                                                 \
        int slot = idx >> 2, q = idx & 3;                                        \
        int kw_ = slot >> 7, r = slot & 127;                                     \
        const int t_ = kh_ * 3 + kw_;                                            \
        size_t wb = ((size_t)t_ * COUT + o0 + r) * CIN + cb_ * 32 + q * 8;       \
        cpa16(base_ + kw_ * B_B + r * AST + q * 16, g_whi + wb, true);           \
    }                                                                            \
} while (0)

    PREF_X(0);
    PREF_B(0); CP_COMMIT();

#pragma unroll 1
    for (int s = 0; s < 48; ++s) {
        const int cb = s / 3;
        const int kh = s - cb * 3;

        if (s + 1 < 48) PREF_B(s + 1);
        if (kh == 0 && cb + 1 < 16) PREF_X(cb + 1);
        CP_COMMIT();
        CP_WAIT1();
        __syncthreads();

        const uint32_t xb    = xsb + (cb & 1) * X_B;
        const uint32_t abase = xb + aoff + (uint32_t)(kh * XROW * XSL);
        const uint32_t bbase = bsb + (s & 1) * BST + boff;

#pragma unroll
        for (int kw = 0; kw < 3; ++kw) {
#pragma unroll
            for (int kc = 0; kc < 2; ++kc) {
                uint32_t bhf[4][2];
#pragma unroll
                for (int nt = 0; nt < 4; ++nt)
                    LDSM_X2(bhf[nt], bbase + kw * B_B + nt * (8 * AST) + kc * 32);
                uint32_t ahf[4][4];
#pragma unroll
                for (int mt = 0; mt < 4; ++mt)
                    LDSM_X4(ahf[mt], abase + (kw + mt * 16) * XSL + kc * 32);
#pragma unroll
                for (int mt = 0; mt < 4; ++mt)
#pragma unroll
                    for (int nt = 0; nt < 4; ++nt)
                        MMA16816(C[mt][nt], ahf[mt], bhf[nt]);
            }
        }
        __syncthreads();
    }
#undef PREF_B
#undef PREF_X

    // ---- epilogue: demod, bias, noise, LeakyReLU ----
    const int h = 4 * by + wm;
#pragma unroll
    for (int mt = 0; mt < 4; ++mt)
#pragma unroll
        for (int nt = 0; nt < 4; ++nt)
#pragma unroll
            for (int i = 0; i < 4; ++i) {
                int wq = mt * 16 + (lid >> 2) + (i >> 1) * 8;
                int o  = wn * 32 + nt * 8 + (lid & 3) * 2 + (i & 1);
                size_t oa = (((size_t)n * COUT + o0 + o) * HH + h) * WW + wq;
                float v = C[mt][nt][i] * dd[o] + bb[o] + noise[oa];
                out[oa] = (v >= 0.f) ? v : 0.2f * v;
            }
}

// ---------------------------------------------------------------------------
extern "C" void kernel_launch(void* const* d_in, const int* in_sizes, int n_in,
                              void* d_out, int out_size) {
    const float* x     = (const float*)d_in[0];
    const float* s     = (const float*)d_in[1];
    const float* noise = (const float*)d_in[2];
    const float* w     = (const float*)d_in[3];
    const float* b     = (const float*)d_in[4];
    float* out = (float*)d_out;

    cudaFuncSetAttribute(conv_mma_kernel,
                         cudaFuncAttributeMaxDynamicSharedMemorySize, SM_DYN);

    prep_x_kernel<<<dim3(8, 64, 16), 256>>>(x, s);
    prep_w_kernel<<<(CIN * COUT + 255) / 256, 256>>>(w);
    d_kernel<<<dim3(COUT / 128, NB), 128>>>(s);
    conv_mma_kernel<<<dim3(COUT / 128, HH / 4, NB), NT, SM_DYN>>>(noise, b, out);
}